// round 7
// baseline (speedup 1.0000x reference)
#include <cuda_runtime.h>

// Problem constants
#define TT 1024   // T: tickers / states
#define MM 8      // M: mesa rank
#define NN 32768  // N: samples
#define DD 32     // D: input dim
#define HH 64     // H: hidden dim
#define SS 2177   // S = H*D + H + O*H + O
#define SP 2192   // padded state row stride (float4-aligned)
#define CAP 128   // bucket capacity per ticker

#define STATE_BLOCKS 288   // 32 t-tiles x 9 dst-tiles
#define SCAT_BLOCKS  32    // 32768 / (4 * 256)

// Scratch (__device__ globals; d_count zero-init at load, reset by k_compute)
__device__ int   d_count[TT];
__device__ int   d_bucket[TT * CAP];
__device__ float d_states[TT * SP];   // rows stored in PERMUTED (wint) order

__device__ __forceinline__ unsigned long long fma2(
    unsigned long long a, unsigned long long b, unsigned long long c) {
    unsigned long long d;
    asm("fma.rn.f32x2 %0, %1, %2, %3;" : "=l"(d) : "l"(a), "l"(b), "l"(c));
    return d;
}

// ---------------------------------------------------------------------------
// k_prep: blocks [0,288) build effective states in PERMUTED layout:
//   row[d], d = j*64 + h  holds  w1_eff[h][j]   (d < 2048)
//   row[d] = state[d] for d in [2048, 2177)  (b1 | w2 | b2, identity)
// blocks [288,320): bucket-scatter samples by ticker.
// ---------------------------------------------------------------------------
__global__ __launch_bounds__(256) void k_prep(
    const int*   __restrict__ ticker,
    const float* __restrict__ mesa,   // (M, T)
    const float* __restrict__ meta,   // (S, M)
    const float* __restrict__ bias,   // (S,)
    const float* __restrict__ base)   // (S,)
{
    int b   = blockIdx.x;
    int tid = threadIdx.x;

    if (b < STATE_BLOCKS) {
        __shared__ float4 sc4[32][2];     // mesa coeffs for 32 tickers
        int tt = b / 9, st = b % 9;
        int t0 = tt * 32;
        {
            int m = tid >> 5, i = tid & 31;
            ((float*)sc4)[i * 8 + m] = mesa[m * TT + t0 + i];
        }
        __syncthreads();

        int d = st * 256 + tid;           // destination index in permuted row
        int s;
        bool ok = true;
        if (d < 2048) {                   // w1 region: d = j*64 + h, s = h*32 + j
            int h = d & 63, j = d >> 6;
            s = h * 32 + j;
        } else {
            s = d;                        // tail: identity
            ok = (d < SS);
        }
        if (ok) {
            const float4* m4 = (const float4*)(meta + s * MM);
            float4 a = m4[0], bq = m4[1];
            float bb = base[s] + bias[s];
#pragma unroll
            for (int i = 0; i < 32; i++) {
                float4 c0 = sc4[i][0];
                float4 c1 = sc4[i][1];
                float v = bb
                    + c0.x * a.x + c0.y * a.y + c0.z * a.z + c0.w * a.w
                    + c1.x * bq.x + c1.y * bq.y + c1.z * bq.z + c1.w * bq.w;
                d_states[(t0 + i) * SP + d] = v;   // coalesced over d
            }
        }
    } else {
        int idx = (b - STATE_BLOCKS) * 256 + tid;
        int4 v = ((const int4*)ticker)[idx];
        int n0 = idx * 4;
        int p;
        p = atomicAdd(&d_count[v.x], 1); if (p < CAP) d_bucket[v.x * CAP + p] = n0;
        p = atomicAdd(&d_count[v.y], 1); if (p < CAP) d_bucket[v.y * CAP + p] = n0 + 1;
        p = atomicAdd(&d_count[v.z], 1); if (p < CAP) d_bucket[v.z * CAP + p] = n0 + 2;
        p = atomicAdd(&d_count[v.w], 1); if (p < CAP) d_bucket[v.w * CAP + p] = n0 + 3;
    }
}

// ---------------------------------------------------------------------------
// k_compute: one BLOCK (4 warps, 128 threads) per ticker.
// Sample-per-lane; warp w owns hidden slice [16w, 16w+16) as 8 f32x2 accs.
// 4096 warps total (vs 1024 in R5) -> latency actually hidden.
// smem floats: [0,2048) wint (j*64+h), [2048,2112) b1, [2112,2176) w2, 2176 b2.
// ---------------------------------------------------------------------------
__global__ __launch_bounds__(128) void k_compute(
    const float* __restrict__ x,
    float* __restrict__ out)
{
    __shared__ __align__(16) float s_w[2180];
    __shared__ float s_x[32 * 33];        // staged x, stride 33 (conflict-free)
    __shared__ float s_part[4][32];       // per-warp partial outputs
    __shared__ int   s_n[32];
    __shared__ int   s_cnt;

    int t    = blockIdx.x;
    int tid  = threadIdx.x;
    int w    = tid >> 5, lane = tid & 31;

    if (tid == 0) { s_cnt = d_count[t]; d_count[t] = 0; }

    // Coalesced copy of the permuted state row (545 float4) by 128 threads.
    const float4* row4 = (const float4*)(d_states + (size_t)t * SP);
    float4* s_w4 = (float4*)s_w;
#pragma unroll
    for (int i = 0; i < 5; i++) {
        int idx = tid + i * 128;
        if (idx < 545) s_w4[idx] = row4[idx];
    }
    __syncthreads();

    int cnt = s_cnt;
    if (cnt == 0) return;
    if (cnt > CAP) cnt = CAP;

    const unsigned long long* b1p =
        (const unsigned long long*)(s_w + 2048);       // b1 as f32x2 pairs
    const float* w2s = s_w + 2112 + w * 16;            // this warp's w2 slice
    float b2 = s_w[2176];

    for (int base = 0; base < cnt; base += 32) {
        if (tid < 32) {
            int idx = base + tid;
            s_n[tid] = d_bucket[t * CAP + (idx < cnt ? idx : cnt - 1)];
        }
        __syncthreads();
        // Stage 32 x-rows cooperatively: 4 warps x 8 rows, coalesced 128B each.
#pragma unroll
        for (int kk = 0; kk < 8; kk++) {
            int k = kk * 4 + w;
            s_x[k * 33 + lane] = x[s_n[k] * DD + lane];
        }
        __syncthreads();

        unsigned long long acc[8];
#pragma unroll
        for (int q = 0; q < 8; q++) acc[q] = b1p[w * 8 + q];

#pragma unroll
        for (int j = 0; j < 32; j++) {
            float xj = s_x[lane * 33 + j];
            unsigned long long xd;
            asm("mov.b64 %0, {%1, %1};" : "=l"(xd) : "f"(xj));
            const ulonglong2* wr = (const ulonglong2*)(s_w + j * 64 + w * 16);
#pragma unroll
            for (int q2 = 0; q2 < 4; q2++) {
                ulonglong2 wv = wr[q2];               // broadcast LDS.128
                acc[2 * q2]     = fma2(wv.x, xd, acc[2 * q2]);
                acc[2 * q2 + 1] = fma2(wv.y, xd, acc[2 * q2 + 1]);
            }
        }

        float o = 0.f;
#pragma unroll
        for (int q = 0; q < 8; q++) {
            float lo = __uint_as_float((unsigned)(acc[q] & 0xffffffffu));
            float hi = __uint_as_float((unsigned)(acc[q] >> 32));
            o += fmaxf(lo, 0.f) * w2s[2 * q]
               + fmaxf(hi, 0.f) * w2s[2 * q + 1];
        }
        s_part[w][lane] = o;
        __syncthreads();

        if (w == 0) {
            int idx = base + lane;
            if (idx < cnt) {
                float oo = b2 + s_part[0][lane] + s_part[1][lane]
                              + s_part[2][lane] + s_part[3][lane];
                out[s_n[lane]] = oo;
            }
        }
        __syncthreads();   // protect s_n/s_x before next group's overwrite
    }
}

extern "C" void kernel_launch(void* const* d_in, const int* in_sizes, int n_in,
                              void* d_out, int out_size) {
    const float* x    = (const float*)d_in[0];
    const int*   tick = (const int*)d_in[1];
    const float* mesa = (const float*)d_in[2];   // (M, T)
    const float* meta = (const float*)d_in[3];   // (S, M)
    const float* bias = (const float*)d_in[4];   // (S,)
    const float* base = (const float*)d_in[5];   // (S,)
    float* out = (float*)d_out;                  // (N, 1) float32

    k_prep<<<STATE_BLOCKS + SCAT_BLOCKS, 256>>>(tick, mesa, meta, bias, base);
    k_compute<<<TT, 128>>>(x, out);
}

// round 8
// speedup vs baseline: 1.0292x; 1.0292x over previous
#include <cuda_runtime.h>

// Problem constants
#define TT 1024   // T: tickers / states
#define MM 8      // M: mesa rank
#define NN 32768  // N: samples
#define DD 32     // D: input dim
#define HH 64     // H: hidden dim
#define SS 2177   // S = H*D + H + O*H + O
#define SP 2192   // padded state row stride (float4-aligned)
#define CAP 128   // bucket capacity per ticker

#define STATE_BLOCKS 288   // 32 t-tiles x 9 dst-tiles
#define SCAT_BLOCKS  32    // 32768 / (4 * 256)

// Scratch (__device__ globals; d_count zero-init at load, reset by k_compute)
__device__ int   d_count[TT];
__device__ int   d_bucket[TT * CAP];
__device__ float d_states[TT * SP];   // rows stored in PERMUTED (wint) order

__device__ __forceinline__ unsigned long long fma2(
    unsigned long long a, unsigned long long b, unsigned long long c) {
    unsigned long long d;
    asm("fma.rn.f32x2 %0, %1, %2, %3;" : "=l"(d) : "l"(a), "l"(b), "l"(c));
    return d;
}
__device__ __forceinline__ unsigned long long dup2(float v) {
    unsigned long long d;
    asm("mov.b64 %0, {%1, %1};" : "=l"(d) : "f"(v));
    return d;
}

// ---------------------------------------------------------------------------
// k_prep: blocks [0,288) build effective states in PERMUTED layout:
//   row[d], d = j*64 + h  holds  w1_eff[h][j]   (d < 2048)
//   row[d] = state[d] for d in [2048, 2177)  (b1 | w2 | b2, identity)
// blocks [288,320): bucket-scatter samples by ticker.
// ---------------------------------------------------------------------------
__global__ __launch_bounds__(256) void k_prep(
    const int*   __restrict__ ticker,
    const float* __restrict__ mesa,   // (M, T)
    const float* __restrict__ meta,   // (S, M)
    const float* __restrict__ bias,   // (S,)
    const float* __restrict__ base)   // (S,)
{
    int b   = blockIdx.x;
    int tid = threadIdx.x;

    if (b < STATE_BLOCKS) {
        __shared__ float4 sc4[32][2];     // mesa coeffs for 32 tickers
        int tt = b / 9, st = b % 9;
        int t0 = tt * 32;
        {
            int m = tid >> 5, i = tid & 31;
            ((float*)sc4)[i * 8 + m] = mesa[m * TT + t0 + i];
        }
        __syncthreads();

        int d = st * 256 + tid;           // destination index in permuted row
        int s;
        bool ok = true;
        if (d < 2048) {                   // w1 region: d = j*64 + h, s = h*32 + j
            int h = d & 63, j = d >> 6;
            s = h * 32 + j;
        } else {
            s = d;                        // tail: identity
            ok = (d < SS);
        }
        if (ok) {
            const float4* m4 = (const float4*)(meta + s * MM);
            float4 a = m4[0], bq = m4[1];
            float bb = base[s] + bias[s];
#pragma unroll
            for (int i = 0; i < 32; i++) {
                float4 c0 = sc4[i][0];
                float4 c1 = sc4[i][1];
                float v = bb
                    + c0.x * a.x + c0.y * a.y + c0.z * a.z + c0.w * a.w
                    + c1.x * bq.x + c1.y * bq.y + c1.z * bq.z + c1.w * bq.w;
                d_states[(t0 + i) * SP + d] = v;   // coalesced over d
            }
        }
    } else {
        int idx = (b - STATE_BLOCKS) * 256 + tid;
        int4 v = ((const int4*)ticker)[idx];
        int n0 = idx * 4;
        int p;
        p = atomicAdd(&d_count[v.x], 1); if (p < CAP) d_bucket[v.x * CAP + p] = n0;
        p = atomicAdd(&d_count[v.y], 1); if (p < CAP) d_bucket[v.y * CAP + p] = n0 + 1;
        p = atomicAdd(&d_count[v.z], 1); if (p < CAP) d_bucket[v.z * CAP + p] = n0 + 2;
        p = atomicAdd(&d_count[v.w], 1); if (p < CAP) d_bucket[v.w * CAP + p] = n0 + 3;
    }
}

// ---------------------------------------------------------------------------
// k_compute: one independent WARP per ticker (grid=1024, block=32).
// Sample-per-lane. Hidden dim processed in TWO sequential passes of 16 f32x2
// accumulators each -> ~90 regs, leaving headroom for ptxas to pipeline the
// 29-cycle LDS latency (R5's 134-reg version could not).
// smem floats: s_w [0,2048) wint (j*64+h), [2048,2112) b1, [2112,2176) w2,
//              2176 b2.  s_x: 32 rows x stride 36 (conflict-free for both
//              coalesced STS and per-lane LDS.128).
// ---------------------------------------------------------------------------
__global__ __launch_bounds__(32) void k_compute(
    const float* __restrict__ x,
    float* __restrict__ out)
{
    __shared__ __align__(16) float s_w[2180];
    __shared__ __align__(16) float s_x[32 * 36];
    __shared__ int s_n[32];

    int t    = blockIdx.x;
    int lane = threadIdx.x;

    // Coalesced copy of the permuted state row (545 float4).
    const float4* row4 = (const float4*)(d_states + (size_t)t * SP);
    float4* s_w4 = (float4*)s_w;
#pragma unroll
    for (int i = 0; i < 18; i++) {
        int idx = lane + i * 32;
        if (idx < 545) s_w4[idx] = row4[idx];
    }

    int cnt = 0;
    if (lane == 0) { cnt = d_count[t]; d_count[t] = 0; }
    cnt = __shfl_sync(0xffffffffu, cnt, 0);
    if (cnt > CAP) cnt = CAP;
    __syncwarp();
    if (cnt == 0) return;

    const unsigned long long* b1p =
        (const unsigned long long*)(s_w + 2048);   // b1 as f32x2 pairs
    float b2 = s_w[2176];

    for (int base = 0; base < cnt; base += 32) {
        int idx = base + lane;
        bool valid = idx < cnt;
        int n = d_bucket[t * CAP + (valid ? idx : cnt - 1)];

        __syncwarp();                 // previous pass done with s_n/s_x
        s_n[lane] = n;
        __syncwarp();
#pragma unroll
        for (int k = 0; k < 32; k++) {
            int nk = s_n[k];          // broadcast LDS
            s_x[k * 36 + lane] = x[nk * DD + lane];   // coalesced 128B rows
        }
        __syncwarp();

        float o = b2;
#pragma unroll 1                       // passes strictly sequential (reg reuse)
        for (int pass = 0; pass < 2; pass++) {
            int h0 = pass * 32;
            unsigned long long acc[16];
#pragma unroll
            for (int q = 0; q < 16; q++) acc[q] = b1p[pass * 16 + q];

            const float4* myx = (const float4*)(s_x + lane * 36);
#pragma unroll
            for (int jq = 0; jq < 8; jq++) {
                float4 xq = myx[jq];                   // own-row LDS.128
                float xe[4] = {xq.x, xq.y, xq.z, xq.w};
#pragma unroll
                for (int e = 0; e < 4; e++) {
                    int j = jq * 4 + e;
                    unsigned long long xd = dup2(xe[e]);
                    const ulonglong2* wr =
                        (const ulonglong2*)(s_w + j * 64 + h0);
#pragma unroll
                    for (int q2 = 0; q2 < 8; q2++) {
                        ulonglong2 wv = wr[q2];        // broadcast LDS.128
                        acc[2 * q2]     = fma2(wv.x, xd, acc[2 * q2]);
                        acc[2 * q2 + 1] = fma2(wv.y, xd, acc[2 * q2 + 1]);
                    }
                }
            }
            const float* w2p = s_w + 2112 + h0;
#pragma unroll
            for (int q = 0; q < 16; q++) {
                float lo = __uint_as_float((unsigned)(acc[q] & 0xffffffffu));
                float hi = __uint_as_float((unsigned)(acc[q] >> 32));
                o += fmaxf(lo, 0.f) * w2p[2 * q]
                   + fmaxf(hi, 0.f) * w2p[2 * q + 1];
            }
        }
        if (valid) out[n] = o;
    }
}

extern "C" void kernel_launch(void* const* d_in, const int* in_sizes, int n_in,
                              void* d_out, int out_size) {
    const float* x    = (const float*)d_in[0];
    const int*   tick = (const int*)d_in[1];
    const float* mesa = (const float*)d_in[2];   // (M, T)
    const float* meta = (const float*)d_in[3];   // (S, M)
    const float* bias = (const float*)d_in[4];   // (S,)
    const float* base = (const float*)d_in[5];   // (S,)
    float* out = (float*)d_out;                  // (N, 1) float32

    k_prep<<<STATE_BLOCKS + SCAT_BLOCKS, 256>>>(tick, mesa, meta, bias, base);
    k_compute<<<TT, 32>>>(x, out);
}